// round 14
// baseline (speedup 1.0000x reference)
#include <cuda_runtime.h>
#include <stdint.h>
#include <math.h>

// Problem constants (fixed by dataset)
#define MAXN 100000
#define MAXE 3200000
#define FIN  128
#define HID  64
#define NBW  ((MAXN + 31) / 32)   // bitmap words

// ---------------- static device scratch ------------------------------------
// Zero at load; k_final re-zeroes everything dirtied, so each graph replay
// starts from the same state.
__device__ int      d_deg[MAXN];
__device__ float    d_dinv[MAXN];
__device__ unsigned d_isout_bits[NBW];   // 12.5 KB
__device__ unsigned d_need_bits[NBW];    // 12.5 KB
__device__ int      d_slot[MAXN];        // node -> compact slot (valid iff needed)
__device__ int      d_slotnode[MAXN];    // slot -> node
__device__ __align__(16) float d_xagg[(size_t)MAXN * FIN];
__device__ float    d_tval[MAXN];        // per-slot scalar t = relu(h1)@W2
__device__ int2     d_l2[MAXE];          // edges whose dst is an output node
__device__ int      d_outnodes[MAXN];
__device__ int      d_nslots;
__device__ int      d_nl2;
__device__ int      d_nout;

__device__ __forceinline__ void red_add_v4(float* addr, float a, float b, float c, float d) {
    asm volatile("red.global.add.v4.f32 [%0], {%1,%2,%3,%4};"
                 :: "l"(addr), "f"(a), "f"(b), "f"(c), "f"(d) : "memory");
}

__device__ __forceinline__ int test_bit(const unsigned* bits, int i) {
    return (bits[i >> 5] >> (i & 31)) & 1u;
}

// ---------------------------------------------------------------------------
// output nodes (last of each graph in sorted batch); also init out[] with bias
__global__ void k_mark(const int* __restrict__ batch, int N,
                       float* __restrict__ out, const float* __restrict__ b2, int G) {
    int i = blockIdx.x * blockDim.x + threadIdx.x;
    if (i < G) out[i] = b2[0];
    if (i >= N) return;
    bool last = (i == N - 1) || (batch[i] != batch[i + 1]);
    if (last) {
        atomicOr(&d_isout_bits[i >> 5], 1u << (i & 31));
        atomicOr(&d_need_bits[i >> 5], 1u << (i & 31));
        int o = atomicAdd(&d_nout, 1);
        d_outnodes[o] = i;
    }
}

__device__ __forceinline__ void pass1_one(int sj, int dj) {
    atomicAdd(&d_deg[dj], 1);
    if (test_bit(d_isout_bits, dj)) {
        int p = atomicAdd(&d_nl2, 1);
        d_l2[p] = make_int2(sj, dj);
        atomicOr(&d_need_bits[sj >> 5], 1u << (sj & 31));
    }
}

// fused: in-degree histogram + layer-2 edge collection, 4 edges/thread
__global__ void k_pass1_v4(const int4* __restrict__ src4, const int4* __restrict__ dst4, int E4) {
    int i = blockIdx.x * blockDim.x + threadIdx.x;
    if (i >= E4) return;
    int4 s = __ldg(&src4[i]);
    int4 d = __ldg(&dst4[i]);
    pass1_one(s.x, d.x);
    pass1_one(s.y, d.y);
    pass1_one(s.z, d.z);
    pass1_one(s.w, d.w);
}
// scalar fallback
__global__ void k_pass1_s(const int* __restrict__ src, const int* __restrict__ dst, int E) {
    int i = blockIdx.x * blockDim.x + threadIdx.x;
    if (i >= E) return;
    pass1_one(__ldg(&src[i]), __ldg(&dst[i]));
}

// dinv for all nodes; slot + xagg zero for needed nodes
__global__ void k_slots(int N) {
    int i = blockIdx.x * blockDim.x + threadIdx.x;
    if (i >= N) return;
    d_dinv[i] = rsqrtf((float)(d_deg[i] + 1));
    if (test_bit(d_need_bits, i)) {
        int s = atomicAdd(&d_nslots, 1);
        d_slot[i] = s;
        d_slotnode[s] = i;
        float4* row = (float4*)&d_xagg[(size_t)s * FIN];
        #pragma unroll
        for (int k = 0; k < FIN / 4; k++) row[k] = make_float4(0.f, 0.f, 0.f, 0.f);
    }
}

// scan all edges (int4: 4 edges/thread); edges into needed nodes ->
// warp-cooperative red.v4 scatter of x[src]*dinv[src] into xagg[slot[dst]]
__global__ void k_gather_v4(const int* __restrict__ src, const int4* __restrict__ dst4,
                            const float4* __restrict__ x4, int E4) {
    int idx  = blockIdx.x * blockDim.x + threadIdx.x;
    int lane = threadIdx.x & 31;
    bool in = idx < E4;
    int4 dd = make_int4(0, 0, 0, 0);
    if (in) dd = __ldg(&dst4[idx]);
    #pragma unroll
    for (int c = 0; c < 4; c++) {
        int d = (c == 0) ? dd.x : (c == 1) ? dd.y : (c == 2) ? dd.z : dd.w;
        int pred = in && test_bit(d_need_bits, d);   // 12.5 KB bitmap: L1 hit
        int s = 0;
        if (pred) s = __ldg(&src[4 * idx + c]);
        unsigned mask = __ballot_sync(0xffffffffu, pred);
        while (mask) {
            int b = __ffs(mask) - 1;
            mask &= mask - 1;
            int bs = __shfl_sync(0xffffffffu, s, b);
            int bd = __shfl_sync(0xffffffffu, d, b);
            int sl = d_slot[bd];
            float w = d_dinv[bs];
            float4 xv = __ldg(&x4[(size_t)bs * (FIN / 4) + lane]);
            red_add_v4(&d_xagg[(size_t)sl * FIN + lane * 4],
                       xv.x * w, xv.y * w, xv.z * w, xv.w * w);
        }
    }
}
// scalar fallback
__global__ void k_gather_s(const int* __restrict__ src, const int* __restrict__ dst,
                           const float4* __restrict__ x4, int E) {
    int idx  = blockIdx.x * blockDim.x + threadIdx.x;
    int lane = threadIdx.x & 31;
    int s = 0, d = 0, pred = 0;
    if (idx < E) {
        d = __ldg(&dst[idx]);
        pred = test_bit(d_need_bits, d);
        if (pred) s = __ldg(&src[idx]);
    }
    unsigned mask = __ballot_sync(0xffffffffu, pred);
    while (mask) {
        int b = __ffs(mask) - 1;
        mask &= mask - 1;
        int bs = __shfl_sync(0xffffffffu, s, b);
        int bd = __shfl_sync(0xffffffffu, d, b);
        int sl = d_slot[bd];
        float w = d_dinv[bs];
        float4 xv = __ldg(&x4[(size_t)bs * (FIN / 4) + lane]);
        red_add_v4(&d_xagg[(size_t)sl * FIN + lane * 4],
                   xv.x * w, xv.y * w, xv.z * w, xv.w * w);
    }
}

// per needed node: y = xagg*dinv + x*dinv^2 ; h1 = relu(y@W1+b1) ; t = h1@W2
__global__ void k_compute(const float* __restrict__ x,
                          const float* __restrict__ W1,
                          const float* __restrict__ b1,
                          const float* __restrict__ W2) {
    __shared__ float ysh[FIN];
    __shared__ float redsh[HID];
    int ns = d_nslots;
    int t  = threadIdx.x;   // 0..63
    for (int s = blockIdx.x; s < ns; s += gridDim.x) {
        int v = d_slotnode[s];
        float dv  = d_dinv[v];
        float dv2 = dv * dv;
        #pragma unroll
        for (int k = t; k < FIN; k += HID)
            ysh[k] = d_xagg[(size_t)s * FIN + k] * dv + x[(size_t)v * FIN + k] * dv2;
        __syncthreads();
        float acc = 0.f;
        #pragma unroll 16
        for (int k = 0; k < FIN; k++)
            acc = fmaf(ysh[k], W1[k * HID + t], acc);
        float h = fmaxf(acc + b1[t], 0.f);
        redsh[t] = h * W2[t];
        __syncthreads();
        if (t < 32) {
            float p = redsh[t] + redsh[t + 32];
            #pragma unroll
            for (int o = 16; o > 0; o >>= 1)
                p += __shfl_down_sync(0xffffffffu, p, o);
            if (t == 0) d_tval[s] = p;
        }
        __syncthreads();
    }
}

// layer-2 edge aggregation + self-loop terms (blocks 0/1) and scratch
// re-zeroing for the next graph replay (all blocks).
__global__ void k_final(const int* __restrict__ batch, float* __restrict__ out) {
    int i = blockIdx.x * blockDim.x + threadIdx.x;
    if (blockIdx.x == 0) {
        int n1 = d_nl2;
        for (int k = threadIdx.x; k < n1; k += blockDim.x) {
            int2 e = d_l2[k];
            float val = d_tval[d_slot[e.x]] * d_dinv[e.x] * d_dinv[e.y];
            atomicAdd(&out[batch[e.y]], val);
        }
        __syncthreads();
        if (threadIdx.x == 0) d_nl2 = 0;
    } else if (blockIdx.x == 1) {
        int n2 = d_nout;
        for (int k = threadIdx.x; k < n2; k += blockDim.x) {
            int v = d_outnodes[k];
            float dv = d_dinv[v];
            atomicAdd(&out[batch[v]], d_tval[d_slot[v]] * dv * dv);
        }
        __syncthreads();
        if (threadIdx.x == 0) { d_nout = 0; d_nslots = 0; }
    }
    if (i < MAXN) d_deg[i] = 0;
    if (i < NBW) { d_isout_bits[i] = 0u; d_need_bits[i] = 0u; }
}

// ---------------------------------------------------------------------------
extern "C" void kernel_launch(void* const* d_in, const int* in_sizes, int n_in,
                              void* d_out, int out_size) {
    const float* x     = (const float*)d_in[0];
    const int*   ei    = (const int*)  d_in[1];
    const int*   batch = (const int*)  d_in[2];
    const float* W1    = (const float*)d_in[3];
    const float* b1    = (const float*)d_in[4];
    const float* W2    = (const float*)d_in[5];
    const float* b2    = (const float*)d_in[6];
    float* out = (float*)d_out;

    const int N = in_sizes[2];
    const int E = in_sizes[1] / 2;
    const int G = out_size;

    const int* src = ei;
    const int* dst = ei + E;

    int gN = (N + 255) / 256;

    k_mark<<<gN, 256>>>(batch, N, out, b2, G);

    bool vec_ok = ((E & 3) == 0) &&
                  ((((uintptr_t)src) & 15) == 0) && ((((uintptr_t)dst) & 15) == 0);
    if (vec_ok) {
        int E4 = E / 4;
        int gE4 = (E4 + 255) / 256;
        k_pass1_v4 <<<gE4, 256>>>((const int4*)src, (const int4*)dst, E4);
        k_slots    <<<gN, 256>>>(N);
        k_gather_v4<<<gE4, 256>>>(src, (const int4*)dst, (const float4*)x, E4);
    } else {
        int gE = (E + 255) / 256;
        k_pass1_s <<<gE, 256>>>(src, dst, E);
        k_slots   <<<gN, 256>>>(N);
        k_gather_s<<<gE, 256>>>(src, dst, (const float4*)x, E);
    }

    k_compute<<<2048, HID>>>(x, W1, b1, W2);
    k_final  <<<gN, 256>>>(batch, out);
}

// round 15
// speedup vs baseline: 1.0542x; 1.0542x over previous
#include <cuda_runtime.h>
#include <stdint.h>
#include <math.h>

// Problem constants (fixed by dataset)
#define MAXN 100000
#define MAXE 3200000
#define FIN  128
#define HID  64
#define NBW  ((MAXN + 31) / 32)   // bitmap words

// ---------------- static device scratch (no dynamic allocation) -------------
__device__ int      d_deg[MAXN];
__device__ unsigned d_isout_bits[NBW];   // 12.5 KB
__device__ unsigned d_need_bits[NBW];    // 12.5 KB
__device__ int      d_slot[MAXN];        // node -> compact slot (valid iff needed)
__device__ int      d_slotnode[MAXN];    // slot -> node
__device__ __align__(16) float d_xagg[(size_t)MAXN * FIN];
__device__ float    d_tval[MAXN];        // per-slot scalar t = relu(h1)@W2
__device__ float    d_sdinv[MAXN];       // per-slot dinv (written by k_compute)
__device__ int2     d_l2[MAXE];          // edges whose dst is an output node
__device__ int      d_outnodes[MAXN];
__device__ int      d_nslots;
__device__ int      d_nl2;
__device__ int      d_nout;

__device__ __forceinline__ void red_add_v4(float* addr, float a, float b, float c, float d) {
    asm volatile("red.global.add.v4.f32 [%0], {%1,%2,%3,%4};"
                 :: "l"(addr), "f"(a), "f"(b), "f"(c), "f"(d) : "memory");
}

__device__ __forceinline__ int test_bit(const unsigned* bits, int i) {
    return (bits[i >> 5] >> (i & 31)) & 1u;
}

__device__ __forceinline__ void zero_row(int s) {
    float4* row = (float4*)&d_xagg[(size_t)s * FIN];
    #pragma unroll
    for (int k = 0; k < FIN / 4; k++) row[k] = make_float4(0.f, 0.f, 0.f, 0.f);
}

// ---------------------------------------------------------------------------
__global__ void k_init(int N) {
    int i = blockIdx.x * blockDim.x + threadIdx.x;
    if (i < N) d_deg[i] = 0;
    if (i < NBW) { d_isout_bits[i] = 0u; d_need_bits[i] = 0u; }
    if (i == 0) { d_nslots = 0; d_nl2 = 0; d_nout = 0; }
}

// output nodes (last of each graph in sorted batch); slot+row-zero for them;
// also init out[] with bias
__global__ void k_mark(const int* __restrict__ batch, int N,
                       float* __restrict__ out, const float* __restrict__ b2, int G) {
    int i = blockIdx.x * blockDim.x + threadIdx.x;
    if (i < G) out[i] = b2[0];
    if (i >= N) return;
    bool last = (i == N - 1) || (batch[i] != batch[i + 1]);
    if (last) {
        atomicOr(&d_isout_bits[i >> 5], 1u << (i & 31));
        atomicOr(&d_need_bits[i >> 5], 1u << (i & 31));
        int s = atomicAdd(&d_nslots, 1);
        d_slot[i] = s;
        d_slotnode[s] = i;
        zero_row(s);
        int o = atomicAdd(&d_nout, 1);
        d_outnodes[o] = i;
    }
}

__device__ __forceinline__ void pass1_one(int sj, int dj) {
    atomicAdd(&d_deg[dj], 1);
    if (test_bit(d_isout_bits, dj)) {
        int p = atomicAdd(&d_nl2, 1);
        d_l2[p] = make_int2(sj, dj);
        unsigned bit = 1u << (sj & 31);
        unsigned old = atomicOr(&d_need_bits[sj >> 5], bit);
        if (!(old & bit)) {                 // atomicOr winner assigns + zeroes
            int s = atomicAdd(&d_nslots, 1);
            d_slot[sj] = s;
            d_slotnode[s] = sj;
            zero_row(s);
        }
    }
}

// fused: in-degree histogram + layer-2 edge collection + V1 slot set
__global__ void k_pass1_v4(const int4* __restrict__ src4, const int4* __restrict__ dst4, int E4) {
    int i = blockIdx.x * blockDim.x + threadIdx.x;
    if (i >= E4) return;
    int4 s = __ldg(&src4[i]);
    int4 d = __ldg(&dst4[i]);
    pass1_one(s.x, d.x);
    pass1_one(s.y, d.y);
    pass1_one(s.z, d.z);
    pass1_one(s.w, d.w);
}
// scalar fallback
__global__ void k_pass1_s(const int* __restrict__ src, const int* __restrict__ dst, int E) {
    int i = blockIdx.x * blockDim.x + threadIdx.x;
    if (i >= E) return;
    pass1_one(__ldg(&src[i]), __ldg(&dst[i]));
}

// scan all edges (int4: 4 edges/thread); edges into needed nodes ->
// warp-cooperative red.v4 scatter of x[src]*rsqrt(deg[src]+1)
__global__ void k_gather_v4(const int* __restrict__ src, const int4* __restrict__ dst4,
                            const float4* __restrict__ x4, int E4) {
    int idx  = blockIdx.x * blockDim.x + threadIdx.x;
    int lane = threadIdx.x & 31;
    bool in = idx < E4;
    int4 dd = make_int4(0, 0, 0, 0);
    if (in) dd = __ldg(&dst4[idx]);
    #pragma unroll
    for (int c = 0; c < 4; c++) {
        int d = (c == 0) ? dd.x : (c == 1) ? dd.y : (c == 2) ? dd.z : dd.w;
        int pred = in && test_bit(d_need_bits, d);   // 12.5 KB bitmap: L1 hit
        int s = 0;
        if (pred) s = __ldg(&src[4 * idx + c]);
        unsigned mask = __ballot_sync(0xffffffffu, pred);
        while (mask) {
            int b = __ffs(mask) - 1;
            mask &= mask - 1;
            int bs = __shfl_sync(0xffffffffu, s, b);
            int bd = __shfl_sync(0xffffffffu, d, b);
            int sl = d_slot[bd];
            float w = rsqrtf((float)(__ldg(&d_deg[bs]) + 1));
            float4 xv = __ldg(&x4[(size_t)bs * (FIN / 4) + lane]);
            red_add_v4(&d_xagg[(size_t)sl * FIN + lane * 4],
                       xv.x * w, xv.y * w, xv.z * w, xv.w * w);
        }
    }
}
// scalar fallback
__global__ void k_gather_s(const int* __restrict__ src, const int* __restrict__ dst,
                           const float4* __restrict__ x4, int E) {
    int idx  = blockIdx.x * blockDim.x + threadIdx.x;
    int lane = threadIdx.x & 31;
    int s = 0, d = 0, pred = 0;
    if (idx < E) {
        d = __ldg(&dst[idx]);
        pred = test_bit(d_need_bits, d);
        if (pred) s = __ldg(&src[idx]);
    }
    unsigned mask = __ballot_sync(0xffffffffu, pred);
    while (mask) {
        int b = __ffs(mask) - 1;
        mask &= mask - 1;
        int bs = __shfl_sync(0xffffffffu, s, b);
        int bd = __shfl_sync(0xffffffffu, d, b);
        int sl = d_slot[bd];
        float w = rsqrtf((float)(__ldg(&d_deg[bs]) + 1));
        float4 xv = __ldg(&x4[(size_t)bs * (FIN / 4) + lane]);
        red_add_v4(&d_xagg[(size_t)sl * FIN + lane * 4],
                   xv.x * w, xv.y * w, xv.z * w, xv.w * w);
    }
}

// per needed node: y = xagg*dv + x*dv^2 ; h1 = relu(y@W1+b1) ; t = h1@W2;
// cache dv in d_sdinv[slot] for k_final
__global__ void k_compute(const float* __restrict__ x,
                          const float* __restrict__ W1,
                          const float* __restrict__ b1,
                          const float* __restrict__ W2) {
    __shared__ float ysh[FIN];
    __shared__ float redsh[HID];
    int ns = d_nslots;
    int t  = threadIdx.x;   // 0..63
    for (int s = blockIdx.x; s < ns; s += gridDim.x) {
        int v = d_slotnode[s];
        float dv  = rsqrtf((float)(d_deg[v] + 1));
        float dv2 = dv * dv;
        #pragma unroll
        for (int k = t; k < FIN; k += HID)
            ysh[k] = d_xagg[(size_t)s * FIN + k] * dv + x[(size_t)v * FIN + k] * dv2;
        __syncthreads();
        float acc = 0.f;
        #pragma unroll 16
        for (int k = 0; k < FIN; k++)
            acc = fmaf(ysh[k], W1[k * HID + t], acc);
        float h = fmaxf(acc + b1[t], 0.f);
        redsh[t] = h * W2[t];
        __syncthreads();
        if (t < 32) {
            float p = redsh[t] + redsh[t + 32];
            #pragma unroll
            for (int o = 16; o > 0; o >>= 1)
                p += __shfl_down_sync(0xffffffffu, p, o);
            if (t == 0) { d_tval[s] = p; d_sdinv[s] = dv; }
        }
        __syncthreads();
    }
}

// layer-2 edge aggregation + self-loop terms into the G outputs
// (slot-indexed sdinv: all touched nodes are in V1)
__global__ void k_final(const int* __restrict__ batch, float* __restrict__ out) {
    int n1 = d_nl2, n2 = d_nout;
    int stride = gridDim.x * blockDim.x;
    for (int i = blockIdx.x * blockDim.x + threadIdx.x; i < n1; i += stride) {
        int2 e = d_l2[i];
        int ss = d_slot[e.x], sd = d_slot[e.y];
        atomicAdd(&out[batch[e.y]], d_tval[ss] * d_sdinv[ss] * d_sdinv[sd]);
    }
    for (int i = blockIdx.x * blockDim.x + threadIdx.x; i < n2; i += stride) {
        int v = d_outnodes[i];
        int sv = d_slot[v];
        float dv = d_sdinv[sv];
        atomicAdd(&out[batch[v]], d_tval[sv] * dv * dv);
    }
}

// ---------------------------------------------------------------------------
extern "C" void kernel_launch(void* const* d_in, const int* in_sizes, int n_in,
                              void* d_out, int out_size) {
    const float* x     = (const float*)d_in[0];
    const int*   ei    = (const int*)  d_in[1];
    const int*   batch = (const int*)  d_in[2];
    const float* W1    = (const float*)d_in[3];
    const float* b1    = (const float*)d_in[4];
    const float* W2    = (const float*)d_in[5];
    const float* b2    = (const float*)d_in[6];
    float* out = (float*)d_out;

    const int N = in_sizes[2];
    const int E = in_sizes[1] / 2;
    const int G = out_size;

    const int* src = ei;
    const int* dst = ei + E;

    int gN = (N + 255) / 256;

    k_init<<<gN, 256>>>(N);
    k_mark<<<gN, 256>>>(batch, N, out, b2, G);

    bool vec_ok = ((E & 3) == 0) &&
                  ((((uintptr_t)src) & 15) == 0) && ((((uintptr_t)dst) & 15) == 0);
    if (vec_ok) {
        int E4 = E / 4;
        int gE4 = (E4 + 255) / 256;
        k_pass1_v4 <<<gE4, 256>>>((const int4*)src, (const int4*)dst, E4);
        k_gather_v4<<<gE4, 256>>>(src, (const int4*)dst, (const float4*)x, E4);
    } else {
        int gE = (E + 255) / 256;
        k_pass1_s <<<gE, 256>>>(src, dst, E);
        k_gather_s<<<gE, 256>>>(src, dst, (const float4*)x, E);
    }

    k_compute<<<2048, HID>>>(x, W1, b1, W2);
    k_final  <<<64, 256>>>(batch, out);
}

// round 17
// speedup vs baseline: 1.0734x; 1.0182x over previous
#include <cuda_runtime.h>
#include <stdint.h>
#include <math.h>

// Problem constants (fixed by dataset)
#define MAXN 100000
#define MAXE 3200000
#define FIN  128
#define HID  64
#define NBW  ((MAXN + 31) / 32)   // bitmap words

// ---------------- static device scratch (no dynamic allocation) -------------
__device__ int      d_deg[MAXN];
__device__ unsigned d_isout_bits[NBW];   // 12.5 KB
__device__ unsigned d_need_bits[NBW];    // 12.5 KB
__device__ int      d_slot[MAXN];        // node -> compact slot (valid iff needed)
__device__ int      d_slotnode[MAXN];    // slot -> node
__device__ __align__(16) float d_xagg[(size_t)MAXN * FIN];
__device__ float    d_tval[MAXN];        // per-slot scalar t = relu(h1)@W2
__device__ float    d_sdinv[MAXN];       // per-slot dinv (written by k_compute)
__device__ int2     d_l2[MAXE];          // edges whose dst is an output node
__device__ int      d_outnodes[MAXN];
__device__ int      d_nslots;
__device__ int      d_nl2;
__device__ int      d_nout;

__device__ __forceinline__ void red_add_v4(float* addr, float a, float b, float c, float d) {
    asm volatile("red.global.add.v4.f32 [%0], {%1,%2,%3,%4};"
                 :: "l"(addr), "f"(a), "f"(b), "f"(c), "f"(d) : "memory");
}

__device__ __forceinline__ int test_bit(const unsigned* bits, int i) {
    return (bits[i >> 5] >> (i & 31)) & 1u;
}

__device__ __forceinline__ void zero_row(int s) {
    float4* row = (float4*)&d_xagg[(size_t)s * FIN];
    #pragma unroll
    for (int k = 0; k < FIN / 4; k++) row[k] = make_float4(0.f, 0.f, 0.f, 0.f);
}

// ---------------------------------------------------------------------------
__global__ void k_init(int N) {
    int i = blockIdx.x * blockDim.x + threadIdx.x;
    if (i < N) d_deg[i] = 0;
    if (i < NBW) { d_isout_bits[i] = 0u; d_need_bits[i] = 0u; }
    if (i == 0) { d_nslots = 0; d_nl2 = 0; d_nout = 0; }
}

// output nodes (last of each graph in sorted batch); slot+row-zero for them;
// also init out[] with bias
__global__ void k_mark(const int* __restrict__ batch, int N,
                       float* __restrict__ out, const float* __restrict__ b2, int G) {
    int i = blockIdx.x * blockDim.x + threadIdx.x;
    if (i < G) out[i] = b2[0];
    if (i >= N) return;
    bool last = (i == N - 1) || (batch[i] != batch[i + 1]);
    if (last) {
        atomicOr(&d_isout_bits[i >> 5], 1u << (i & 31));
        atomicOr(&d_need_bits[i >> 5], 1u << (i & 31));
        int s = atomicAdd(&d_nslots, 1);
        d_slot[i] = s;
        d_slotnode[s] = i;
        zero_row(s);
        int o = atomicAdd(&d_nout, 1);
        d_outnodes[o] = i;
    }
}

// hit path: record layer-2 edge, extend V1 slot set (atomicOr winner zeroes row)
__device__ __forceinline__ void pass1_hit(int sj, int dj) {
    int p = atomicAdd(&d_nl2, 1);
    d_l2[p] = make_int2(sj, dj);
    unsigned bit = 1u << (sj & 31);
    unsigned old = atomicOr(&d_need_bits[sj >> 5], bit);
    if (!(old & bit)) {
        int s = atomicAdd(&d_nslots, 1);
        d_slot[sj] = s;
        d_slotnode[s] = sj;
        zero_row(s);
    }
}

// fused: in-degree histogram + layer-2 edge collection + V1 slot set.
// src loaded LAZILY (hit rate ~0.06%): saves one LDG.128 per 4 edges.
__global__ void k_pass1_v4(const int* __restrict__ src, const int4* __restrict__ dst4, int E4) {
    int i = blockIdx.x * blockDim.x + threadIdx.x;
    if (i >= E4) return;
    int4 d = __ldg(&dst4[i]);
    atomicAdd(&d_deg[d.x], 1);
    atomicAdd(&d_deg[d.y], 1);
    atomicAdd(&d_deg[d.z], 1);
    atomicAdd(&d_deg[d.w], 1);
    if (test_bit(d_isout_bits, d.x)) pass1_hit(__ldg(&src[4 * i + 0]), d.x);
    if (test_bit(d_isout_bits, d.y)) pass1_hit(__ldg(&src[4 * i + 1]), d.y);
    if (test_bit(d_isout_bits, d.z)) pass1_hit(__ldg(&src[4 * i + 2]), d.z);
    if (test_bit(d_isout_bits, d.w)) pass1_hit(__ldg(&src[4 * i + 3]), d.w);
}
// scalar fallback
__global__ void k_pass1_s(const int* __restrict__ src, const int* __restrict__ dst, int E) {
    int i = blockIdx.x * blockDim.x + threadIdx.x;
    if (i >= E) return;
    int dj = __ldg(&dst[i]);
    atomicAdd(&d_deg[dj], 1);
    if (test_bit(d_isout_bits, dj)) pass1_hit(__ldg(&src[i]), dj);
}

// scan all edges (int4: 4 edges/thread); edges into needed nodes ->
// warp-cooperative red.v4 scatter of x[src]*rsqrt(deg[src]+1)
__global__ void k_gather_v4(const int* __restrict__ src, const int4* __restrict__ dst4,
                            const float4* __restrict__ x4, int E4) {
    int idx  = blockIdx.x * blockDim.x + threadIdx.x;
    int lane = threadIdx.x & 31;
    bool in = idx < E4;
    int4 dd = make_int4(0, 0, 0, 0);
    if (in) dd = __ldg(&dst4[idx]);
    #pragma unroll
    for (int c = 0; c < 4; c++) {
        int d = (c == 0) ? dd.x : (c == 1) ? dd.y : (c == 2) ? dd.z : dd.w;
        int pred = in && test_bit(d_need_bits, d);   // 12.5 KB bitmap: L1 hit
        int s = 0;
        if (pred) s = __ldg(&src[4 * idx + c]);
        unsigned mask = __ballot_sync(0xffffffffu, pred);
        while (mask) {
            int b = __ffs(mask) - 1;
            mask &= mask - 1;
            int bs = __shfl_sync(0xffffffffu, s, b);
            int bd = __shfl_sync(0xffffffffu, d, b);
            int sl = d_slot[bd];
            float w = rsqrtf((float)(__ldg(&d_deg[bs]) + 1));
            float4 xv = __ldg(&x4[(size_t)bs * (FIN / 4) + lane]);
            red_add_v4(&d_xagg[(size_t)sl * FIN + lane * 4],
                       xv.x * w, xv.y * w, xv.z * w, xv.w * w);
        }
    }
}
// scalar fallback
__global__ void k_gather_s(const int* __restrict__ src, const int* __restrict__ dst,
                           const float4* __restrict__ x4, int E) {
    int idx  = blockIdx.x * blockDim.x + threadIdx.x;
    int lane = threadIdx.x & 31;
    int s = 0, d = 0, pred = 0;
    if (idx < E) {
        d = __ldg(&dst[idx]);
        pred = test_bit(d_need_bits, d);
        if (pred) s = __ldg(&src[idx]);
    }
    unsigned mask = __ballot_sync(0xffffffffu, pred);
    while (mask) {
        int b = __ffs(mask) - 1;
        mask &= mask - 1;
        int bs = __shfl_sync(0xffffffffu, s, b);
        int bd = __shfl_sync(0xffffffffu, d, b);
        int sl = d_slot[bd];
        float w = rsqrtf((float)(__ldg(&d_deg[bs]) + 1));
        float4 xv = __ldg(&x4[(size_t)bs * (FIN / 4) + lane]);
        red_add_v4(&d_xagg[(size_t)sl * FIN + lane * 4],
                   xv.x * w, xv.y * w, xv.z * w, xv.w * w);
    }
}

// per needed node: y = xagg*dv + x*dv^2 ; h1 = relu(y@W1+b1) ; t = h1@W2;
// cache dv in d_sdinv[slot] for k_final
__global__ void k_compute(const float* __restrict__ x,
                          const float* __restrict__ W1,
                          const float* __restrict__ b1,
                          const float* __restrict__ W2) {
    __shared__ float ysh[FIN];
    __shared__ float redsh[HID];
    int ns = d_nslots;
    int t  = threadIdx.x;   // 0..63
    for (int s = blockIdx.x; s < ns; s += gridDim.x) {
        int v = d_slotnode[s];
        float dv  = rsqrtf((float)(d_deg[v] + 1));
        float dv2 = dv * dv;
        #pragma unroll
        for (int k = t; k < FIN; k += HID)
            ysh[k] = d_xagg[(size_t)s * FIN + k] * dv + x[(size_t)v * FIN + k] * dv2;
        __syncthreads();
        float acc = 0.f;
        #pragma unroll 16
        for (int k = 0; k < FIN; k++)
            acc = fmaf(ysh[k], W1[k * HID + t], acc);
        float h = fmaxf(acc + b1[t], 0.f);
        redsh[t] = h * W2[t];
        __syncthreads();
        if (t < 32) {
            float p = redsh[t] + redsh[t + 32];
            #pragma unroll
            for (int o = 16; o > 0; o >>= 1)
                p += __shfl_down_sync(0xffffffffu, p, o);
            if (t == 0) { d_tval[s] = p; d_sdinv[s] = dv; }
        }
        __syncthreads();
    }
}

// layer-2 edge aggregation + self-loop terms into the G outputs
// (slot-indexed sdinv: all touched nodes are in V1)
__global__ void k_final(const int* __restrict__ batch, float* __restrict__ out) {
    int n1 = d_nl2, n2 = d_nout;
    int stride = gridDim.x * blockDim.x;
    for (int i = blockIdx.x * blockDim.x + threadIdx.x; i < n1; i += stride) {
        int2 e = d_l2[i];
        int ss = d_slot[e.x], sd = d_slot[e.y];
        atomicAdd(&out[batch[e.y]], d_tval[ss] * d_sdinv[ss] * d_sdinv[sd]);
    }
    for (int i = blockIdx.x * blockDim.x + threadIdx.x; i < n2; i += stride) {
        int v = d_outnodes[i];
        int sv = d_slot[v];
        float dv = d_sdinv[sv];
        atomicAdd(&out[batch[v]], d_tval[sv] * dv * dv);
    }
}

// ---------------------------------------------------------------------------
extern "C" void kernel_launch(void* const* d_in, const int* in_sizes, int n_in,
                              void* d_out, int out_size) {
    const float* x     = (const float*)d_in[0];
    const int*   ei    = (const int*)  d_in[1];
    const int*   batch = (const int*)  d_in[2];
    const float* W1    = (const float*)d_in[3];
    const float* b1    = (const float*)d_in[4];
    const float* W2    = (const float*)d_in[5];
    const float* b2    = (const float*)d_in[6];
    float* out = (float*)d_out;

    const int N = in_sizes[2];
    const int E = in_sizes[1] / 2;
    const int G = out_size;

    const int* src = ei;
    const int* dst = ei + E;

    int gN = (N + 255) / 256;

    k_init<<<gN, 256>>>(N);
    k_mark<<<gN, 256>>>(batch, N, out, b2, G);

    bool vec_ok = ((E & 3) == 0) &&
                  ((((uintptr_t)src) & 15) == 0) && ((((uintptr_t)dst) & 15) == 0);
    if (vec_ok) {
        int E4 = E / 4;
        int gE4 = (E4 + 255) / 256;
        k_pass1_v4 <<<gE4, 256>>>(src, (const int4*)dst, E4);
        k_gather_v4<<<gE4, 256>>>(src, (const int4*)dst, (const float4*)x, E4);
    } else {
        int gE = (E + 255) / 256;
        k_pass1_s <<<gE, 256>>>(src, dst, E);
        k_gather_s<<<gE, 256>>>(src, dst, (const float4*)x, E);
    }

    k_compute<<<2048, HID>>>(x, W1, b1, W2);
    k_final  <<<64, 256>>>(batch, out);
}